// round 5
// baseline (speedup 1.0000x reference)
#include <cuda_runtime.h>
#include <math.h>
#include <mma.h>

using namespace nvcuda;

#define NC 4096
#define NF 16384
#define CC 512
#define CF 256
#define CO 256
#define KTOT 768

// ---------------------------------------------------------------------------
// scratch (device globals: allocation-free)
// ---------------------------------------------------------------------------
__device__ float g_G[NC * CO];       // coarse_features @ Wc^T  (4 MB)
__device__ float g_F[NF * CO];       // fine_features @ Wf^T    (16 MB)
__device__ int   g_idx[NF * 3];
__device__ float g_w[NF * 3];
// tf32 split copies
__device__ float g_cf_hi[NC * CC], g_cf_lo[NC * CC];    // 8 MB x2
__device__ float g_ff_hi[NF * CF], g_ff_lo[NF * CF];    // 16 MB x2
__device__ float g_W_hi[CO * KTOT], g_W_lo[CO * KTOT];  // 0.75 MB x2

__device__ __forceinline__ float to_tf32(float x) {
    unsigned r;
    asm("cvt.rna.tf32.f32 %0, %1;" : "=r"(r) : "f"(x));
    return __uint_as_float(r);
}

// ---------------------------------------------------------------------------
// Split kernel: x -> (hi, lo) tf32 pair.  hi = tf32(x), lo = tf32(x - hi)
// ---------------------------------------------------------------------------
__global__ void split_tf32_kernel(const float* __restrict__ x,
                                  float* __restrict__ hi,
                                  float* __restrict__ lo, int n) {
    int i = blockIdx.x * blockDim.x + threadIdx.x;
    if (i < n) {
        float v = x[i];
        float h = to_tf32(v);
        hi[i] = h;
        lo[i] = to_tf32(v - h);
    }
}

// ---------------------------------------------------------------------------
// Kernel 1: kNN (k=3) with fp64 boundary resolution (unchanged from R3).
// ---------------------------------------------------------------------------
__global__ void knn_kernel(const float* __restrict__ cpos,
                           const float* __restrict__ fpos,
                           int* __restrict__ idx_out,
                           float* __restrict__ w_out) {
    extern __shared__ float4 sc[];
    for (int i = threadIdx.x; i < NC; i += blockDim.x) {
        float x = cpos[3 * i], y = cpos[3 * i + 1], z = cpos[3 * i + 2];
        float cc = __fadd_rn(__fadd_rn(__fmul_rn(x, x), __fmul_rn(y, y)),
                             __fmul_rn(z, z));
        sc[i] = make_float4(x, y, z, cc);
    }
    __syncthreads();

    int n = blockIdx.x * blockDim.x + threadIdx.x;
    float fx = fpos[3 * n], fy = fpos[3 * n + 1], fz = fpos[3 * n + 2];
    float ff = __fadd_rn(__fadd_rn(__fmul_rn(fx, fx), __fmul_rn(fy, fy)),
                         __fmul_rn(fz, fz));

    float b0 = 3.4e38f, b1 = 3.4e38f, b2 = 3.4e38f, b3 = 3.4e38f;
    int   i0 = 0, i1 = 0, i2 = 0, i3 = 0;

#pragma unroll 4
    for (int j = 0; j < NC; j++) {
        float4 c = sc[j];
        float dot = __fmaf_rn(fz, c.z, __fmaf_rn(fy, c.y, __fmul_rn(fx, c.x)));
        float d = __fadd_rn(__fadd_rn(ff, c.w), __fmul_rn(-2.0f, dot));
        if (d < b3) {
            if (d < b2) {
                b3 = b2; i3 = i2;
                if (d < b1) {
                    b2 = b1; i2 = i1;
                    if (d < b0) { b1 = b0; i1 = i0; b0 = d; i0 = j; }
                    else        { b1 = d;  i1 = j; }
                } else {
                    b2 = d; i2 = j;
                }
            } else {
                b3 = d; i3 = j;
            }
        }
    }

    if (b3 - b2 < 1e-5f) {  // ambiguous rank-3/4: exact fp64 direct-form
        double dax = (double)fx - (double)cpos[3 * i2];
        double day = (double)fy - (double)cpos[3 * i2 + 1];
        double daz = (double)fz - (double)cpos[3 * i2 + 2];
        double da = dax * dax + day * day + daz * daz;
        double dbx = (double)fx - (double)cpos[3 * i3];
        double dby = (double)fy - (double)cpos[3 * i3 + 1];
        double dbz = (double)fz - (double)cpos[3 * i3 + 2];
        double db = dbx * dbx + dby * dby + dbz * dbz;
        if (db < da || (db == da && i3 < i2)) { i2 = i3; b2 = b3; }
    }

    float w0 = 1.0f / fmaxf(b0, 1e-16f);
    float w1 = 1.0f / fmaxf(b1, 1e-16f);
    float w2 = 1.0f / fmaxf(b2, 1e-16f);
    float inv = 1.0f / (w0 + w1 + w2);

    idx_out[3 * n]     = i0;
    idx_out[3 * n + 1] = i1;
    idx_out[3 * n + 2] = i2;
    w_out[3 * n]     = w0 * inv;
    w_out[3 * n + 1] = w1 * inv;
    w_out[3 * n + 2] = w2 * inv;
}

// ---------------------------------------------------------------------------
// Kernel 2/3: tensor-core GEMM (3xTF32 split).
//   C[M,N] = A[M,K] * B[N,K]^T,  A,B given as (hi,lo) tf32 pairs.
//   C = Ahi*Bhi + Ahi*Blo + Alo*Bhi  (fp32 accumulate)
// Block: 64x64 tile, 128 threads (4 warps, each 32x32 via 2x2 m16n16k8 frags).
// ---------------------------------------------------------------------------
#define BM 64
#define BN 64
#define BKT 16
#define LDT (BKT + 4)

__global__ __launch_bounds__(128) void gemm_tf32x3(
    const float* __restrict__ Ahi, const float* __restrict__ Alo, int lda,
    const float* __restrict__ Bhi, const float* __restrict__ Blo, int ldb,
    float* __restrict__ C, int ldc, int K) {

    __shared__ float sAhi[BM][LDT], sAlo[BM][LDT];
    __shared__ float sBhi[BN][LDT], sBlo[BN][LDT];

    int tid  = threadIdx.x;
    int warp = tid >> 5;
    int wm = warp >> 1;            // 0..1
    int wn = warp & 1;             // 0..1
    int m0 = blockIdx.y * BM;
    int n0 = blockIdx.x * BN;

    // loader mapping: 128 threads, each loads 2 float4 per matrix per tile
    int lrow  = tid >> 2;          // 0..31
    int lcol4 = (tid & 3) * 4;     // 0,4,8,12

    wmma::fragment<wmma::accumulator, 16, 16, 8, float> acc[2][2];
#pragma unroll
    for (int i = 0; i < 2; i++)
#pragma unroll
        for (int j = 0; j < 2; j++) wmma::fill_fragment(acc[i][j], 0.0f);

    for (int k0 = 0; k0 < K; k0 += BKT) {
#pragma unroll
        for (int r = 0; r < 2; r++) {
            int row = lrow + 32 * r;
            float4 v;
            v = *(const float4*)(Ahi + (size_t)(m0 + row) * lda + k0 + lcol4);
            *(float4*)&sAhi[row][lcol4] = v;
            v = *(const float4*)(Alo + (size_t)(m0 + row) * lda + k0 + lcol4);
            *(float4*)&sAlo[row][lcol4] = v;
            v = *(const float4*)(Bhi + (size_t)(n0 + row) * ldb + k0 + lcol4);
            *(float4*)&sBhi[row][lcol4] = v;
            v = *(const float4*)(Blo + (size_t)(n0 + row) * ldb + k0 + lcol4);
            *(float4*)&sBlo[row][lcol4] = v;
        }
        __syncthreads();

#pragma unroll
        for (int ks = 0; ks < BKT; ks += 8) {
            wmma::fragment<wmma::matrix_a, 16, 16, 8, wmma::precision::tf32,
                           wmma::row_major> ahi[2], alo[2];
            wmma::fragment<wmma::matrix_b, 16, 16, 8, wmma::precision::tf32,
                           wmma::col_major> bhi[2], blo[2];
#pragma unroll
            for (int i = 0; i < 2; i++) {
                int mr = 32 * wm + 16 * i;
                wmma::load_matrix_sync(ahi[i], &sAhi[mr][ks], LDT);
                wmma::load_matrix_sync(alo[i], &sAlo[mr][ks], LDT);
            }
#pragma unroll
            for (int j = 0; j < 2; j++) {
                int nr = 32 * wn + 16 * j;
                wmma::load_matrix_sync(bhi[j], &sBhi[nr][ks], LDT);
                wmma::load_matrix_sync(blo[j], &sBlo[nr][ks], LDT);
            }
#pragma unroll
            for (int i = 0; i < 2; i++)
#pragma unroll
                for (int j = 0; j < 2; j++) {
                    wmma::mma_sync(acc[i][j], ahi[i], bhi[j], acc[i][j]);
                    wmma::mma_sync(acc[i][j], ahi[i], blo[j], acc[i][j]);
                    wmma::mma_sync(acc[i][j], alo[i], bhi[j], acc[i][j]);
                }
        }
        __syncthreads();
    }

#pragma unroll
    for (int i = 0; i < 2; i++)
#pragma unroll
        for (int j = 0; j < 2; j++) {
            float* cp = C + (size_t)(m0 + 32 * wm + 16 * i) * ldc
                          + n0 + 32 * wn + 16 * j;
            wmma::store_matrix_sync(cp, acc[i][j], ldc, wmma::mem_row_major);
        }
}

// ---------------------------------------------------------------------------
// Kernel 4: epilogue — gather 3 rows of G, add F row + bias, ReLU, LayerNorm.
// ---------------------------------------------------------------------------
__global__ __launch_bounds__(CO) void epilogue_kernel(
    const float* __restrict__ G, const float* __restrict__ Fm,
    const int* __restrict__ idx, const float* __restrict__ w,
    const float* __restrict__ bias, const float* __restrict__ gamma,
    const float* __restrict__ beta, float* __restrict__ out) {

    int n = blockIdx.x;
    int o = threadIdx.x;

    int i0 = idx[3 * n], i1 = idx[3 * n + 1], i2 = idx[3 * n + 2];
    float w0 = w[3 * n], w1 = w[3 * n + 1], w2 = w[3 * n + 2];

    float h = w0 * G[(size_t)i0 * CO + o]
            + w1 * G[(size_t)i1 * CO + o]
            + w2 * G[(size_t)i2 * CO + o]
            + Fm[(size_t)n * CO + o] + bias[o];
    h = fmaxf(h, 0.0f);

    float s1 = h, s2 = h * h;
#pragma unroll
    for (int off = 16; off; off >>= 1) {
        s1 += __shfl_xor_sync(0xffffffffu, s1, off);
        s2 += __shfl_xor_sync(0xffffffffu, s2, off);
    }
    __shared__ float p1[8], p2[8], stats[2];
    int warp = o >> 5, lane = o & 31;
    if (lane == 0) { p1[warp] = s1; p2[warp] = s2; }
    __syncthreads();
    if (o == 0) {
        float t1 = 0.f, t2 = 0.f;
#pragma unroll
        for (int i = 0; i < 8; i++) { t1 += p1[i]; t2 += p2[i]; }
        float mu  = t1 * (1.0f / CO);
        float var = t2 * (1.0f / CO) - mu * mu;
        stats[0] = mu;
        stats[1] = rsqrtf(var + 1e-5f);
    }
    __syncthreads();
    float mu = stats[0], rinv = stats[1];
    out[(size_t)n * CO + o] = gamma[o] * (h - mu) * rinv + beta[o];
}

// ---------------------------------------------------------------------------
extern "C" void kernel_launch(void* const* d_in, const int* in_sizes, int n_in,
                              void* d_out, int out_size) {
    const float* cfeat = (const float*)d_in[0];  // [4096, 512]
    const float* cpos  = (const float*)d_in[1];  // [4096, 3]
    const float* ffeat = (const float*)d_in[2];  // [16384, 256]
    const float* fpos  = (const float*)d_in[3];  // [16384, 3]
    const float* W     = (const float*)d_in[4];  // [256, 768]
    const float* bias  = (const float*)d_in[5];  // [256]
    const float* gamma = (const float*)d_in[6];  // [256]
    const float* beta  = (const float*)d_in[7];  // [256]
    float* out = (float*)d_out;

    float *G, *Fm, *wp;
    int* idxp;
    float *cfh, *cfl, *ffh, *ffl, *Wh, *Wl;
    cudaGetSymbolAddress((void**)&G,    g_G);
    cudaGetSymbolAddress((void**)&Fm,   g_F);
    cudaGetSymbolAddress((void**)&idxp, g_idx);
    cudaGetSymbolAddress((void**)&wp,   g_w);
    cudaGetSymbolAddress((void**)&cfh,  g_cf_hi);
    cudaGetSymbolAddress((void**)&cfl,  g_cf_lo);
    cudaGetSymbolAddress((void**)&ffh,  g_ff_hi);
    cudaGetSymbolAddress((void**)&ffl,  g_ff_lo);
    cudaGetSymbolAddress((void**)&Wh,   g_W_hi);
    cudaGetSymbolAddress((void**)&Wl,   g_W_lo);

    // kNN (64 KB dynamic shared: all coarse points as float4)
    cudaFuncSetAttribute(knn_kernel, cudaFuncAttributeMaxDynamicSharedMemorySize,
                         NC * (int)sizeof(float4));
    knn_kernel<<<NF / 128, 128, NC * sizeof(float4)>>>(cpos, fpos, idxp, wp);

    // tf32 splits
    split_tf32_kernel<<<(NC * CC + 255) / 256, 256>>>(cfeat, cfh, cfl, NC * CC);
    split_tf32_kernel<<<(NF * CF + 255) / 256, 256>>>(ffeat, ffh, ffl, NF * CF);
    split_tf32_kernel<<<(CO * KTOT + 255) / 256, 256>>>(W, Wh, Wl, CO * KTOT);

    // G = coarse_features @ Wc^T   (Wc = W[:, :512])
    {
        dim3 grid(CO / BN, NC / BM);
        gemm_tf32x3<<<grid, 128>>>(cfh, cfl, CC, Wh, Wl, KTOT, G, CO, CC);
    }
    // F = fine_features @ Wf^T     (Wf = W[:, 512:768])
    {
        dim3 grid(CO / BN, NF / BM);
        gemm_tf32x3<<<grid, 128>>>(ffh, ffl, CF, Wh + CC, Wl + CC, KTOT, Fm, CO, CF);
    }

    epilogue_kernel<<<NF, CO>>>(G, Fm, idxp, wp, bias, gamma, beta, out);
}

// round 7
// speedup vs baseline: 1.3828x; 1.3828x over previous
#include <cuda_runtime.h>
#include <math.h>

#define NC 4096
#define NF 16384
#define CC 512
#define CF 256
#define CO 256
#define KTOT 768

// scratch (device globals: allocation-free)
__device__ float g_G[NC * CO];     // coarse_features @ Wc^T   (4 MB)
__device__ float g_F[NF * CO];     // fine_features @ Wf^T     (16 MB)
__device__ int   g_idx[NF * 3];
__device__ float g_w[NF * 3];

// ---------------------------------------------------------------------------
// Kernel 1: kNN (k=3) with fp64 boundary resolution (unchanged from R3).
// ---------------------------------------------------------------------------
__global__ void knn_kernel(const float* __restrict__ cpos,
                           const float* __restrict__ fpos,
                           int* __restrict__ idx_out,
                           float* __restrict__ w_out) {
    extern __shared__ float4 sc[];
    for (int i = threadIdx.x; i < NC; i += blockDim.x) {
        float x = cpos[3 * i], y = cpos[3 * i + 1], z = cpos[3 * i + 2];
        float cc = __fadd_rn(__fadd_rn(__fmul_rn(x, x), __fmul_rn(y, y)),
                             __fmul_rn(z, z));
        sc[i] = make_float4(x, y, z, cc);
    }
    __syncthreads();

    int n = blockIdx.x * blockDim.x + threadIdx.x;
    float fx = fpos[3 * n], fy = fpos[3 * n + 1], fz = fpos[3 * n + 2];
    float ff = __fadd_rn(__fadd_rn(__fmul_rn(fx, fx), __fmul_rn(fy, fy)),
                         __fmul_rn(fz, fz));

    float b0 = 3.4e38f, b1 = 3.4e38f, b2 = 3.4e38f, b3 = 3.4e38f;
    int   i0 = 0, i1 = 0, i2 = 0, i3 = 0;

#pragma unroll 4
    for (int j = 0; j < NC; j++) {
        float4 c = sc[j];
        float dot = __fmaf_rn(fz, c.z, __fmaf_rn(fy, c.y, __fmul_rn(fx, c.x)));
        float d = __fadd_rn(__fadd_rn(ff, c.w), __fmul_rn(-2.0f, dot));
        if (d < b3) {
            if (d < b2) {
                b3 = b2; i3 = i2;
                if (d < b1) {
                    b2 = b1; i2 = i1;
                    if (d < b0) { b1 = b0; i1 = i0; b0 = d; i0 = j; }
                    else        { b1 = d;  i1 = j; }
                } else {
                    b2 = d; i2 = j;
                }
            } else {
                b3 = d; i3 = j;
            }
        }
    }

    if (b3 - b2 < 1e-5f) {  // ambiguous rank-3/4: exact fp64 direct-form
        double dax = (double)fx - (double)cpos[3 * i2];
        double day = (double)fy - (double)cpos[3 * i2 + 1];
        double daz = (double)fz - (double)cpos[3 * i2 + 2];
        double da = dax * dax + day * day + daz * daz;
        double dbx = (double)fx - (double)cpos[3 * i3];
        double dby = (double)fy - (double)cpos[3 * i3 + 1];
        double dbz = (double)fz - (double)cpos[3 * i3 + 2];
        double db = dbx * dbx + dby * dby + dbz * dbz;
        if (db < da || (db == da && i3 < i2)) { i2 = i3; b2 = b3; }
    }

    float w0 = 1.0f / fmaxf(b0, 1e-16f);
    float w1 = 1.0f / fmaxf(b1, 1e-16f);
    float w2 = 1.0f / fmaxf(b2, 1e-16f);
    float inv = 1.0f / (w0 + w1 + w2);

    idx_out[3 * n]     = i0;
    idx_out[3 * n + 1] = i1;
    idx_out[3 * n + 2] = i2;
    w_out[3 * n]     = w0 * inv;
    w_out[3 * n + 1] = w1 * inv;
    w_out[3 * n + 2] = w2 * inv;
}

// ---------------------------------------------------------------------------
// Kernel 2: merged dual SGEMM.  C[M,N] = A[M,K]*B[N,K]^T (fp32 SIMT).
// 128x128x16 tiles, 256 threads, 8x8 microtile, double-buffered smem,
// transposed smem (sA[k][m], sB[k][n], pad 4).
// Blocks 0..G_BLOCKS-1 : G = cfeat @ Wc^T   (M=4096, K=512)
// Blocks G_BLOCKS..    : F = ffeat @ Wf^T   (M=16384, K=256)
// ---------------------------------------------------------------------------
#define BM 128
#define BN 128
#define BK 16
#define LDP (BM + 4)
#define G_BLOCKS ((NC / BM) * (CO / BN))   // 32 * 2 = 64
#define F_BLOCKS ((NF / BM) * (CO / BN))   // 128 * 2 = 256

__global__ __launch_bounds__(256, 2) void dual_sgemm(
    const float* __restrict__ cfeat, const float* __restrict__ ffeat,
    const float* __restrict__ W,
    float* __restrict__ G, float* __restrict__ F) {

    __shared__ float sA[2][BK][LDP];
    __shared__ float sB[2][BK][LDP];

    const float* A;
    const float* B;
    float* C;
    int lda, K, m0, n0;
    {
        int bid = blockIdx.x;
        if (bid < G_BLOCKS) {
            int mb = bid >> 1;          // 0..31
            int nb = bid & 1;           // 0..1
            A = cfeat; B = W; C = g_G == nullptr ? G : G; // keep param use
            lda = CC; K = CC;
            m0 = mb * BM; n0 = nb * BN;
            C = G;
        } else {
            bid -= G_BLOCKS;
            int mb = bid >> 1;          // 0..127
            int nb = bid & 1;
            A = ffeat; B = W + CC;
            lda = CF; K = CF;
            m0 = mb * BM; n0 = nb * BN;
            C = F;
        }
    }
    const int ldb = KTOT;

    int tid = threadIdx.x;
    // loader mapping: 256 threads; row = tid>>1 (0..127), k4 = (tid&1)*8
    int lrow = tid >> 1;
    int lk   = (tid & 1) * 8;
    // compute mapping: tx (n) 0..15, ty (m) 0..15
    int tx = tid & 15, ty = tid >> 4;

    const float* Aptr = A + (size_t)(m0 + lrow) * lda + lk;
    const float* Bptr = B + (size_t)(n0 + lrow) * ldb + lk;

    float acc[8][8] = {};

    // prologue: load tile 0 into buffer 0
    {
        float4 a0 = *(const float4*)(Aptr);
        float4 a1 = *(const float4*)(Aptr + 4);
        float4 b0 = *(const float4*)(Bptr);
        float4 b1 = *(const float4*)(Bptr + 4);
        sA[0][lk + 0][lrow] = a0.x; sA[0][lk + 1][lrow] = a0.y;
        sA[0][lk + 2][lrow] = a0.z; sA[0][lk + 3][lrow] = a0.w;
        sA[0][lk + 4][lrow] = a1.x; sA[0][lk + 5][lrow] = a1.y;
        sA[0][lk + 6][lrow] = a1.z; sA[0][lk + 7][lrow] = a1.w;
        sB[0][lk + 0][lrow] = b0.x; sB[0][lk + 1][lrow] = b0.y;
        sB[0][lk + 2][lrow] = b0.z; sB[0][lk + 3][lrow] = b0.w;
        sB[0][lk + 4][lrow] = b1.x; sB[0][lk + 5][lrow] = b1.y;
        sB[0][lk + 6][lrow] = b1.z; sB[0][lk + 7][lrow] = b1.w;
    }
    __syncthreads();

    int nsteps = K / BK;
    int buf = 0;
    for (int s = 0; s < nsteps; s++) {
        float4 a0, a1, b0, b1;
        bool more = (s + 1 < nsteps);
        if (more) {
            const float* Ap = Aptr + (s + 1) * BK;
            const float* Bp = Bptr + (s + 1) * BK;
            a0 = *(const float4*)(Ap);
            a1 = *(const float4*)(Ap + 4);
            b0 = *(const float4*)(Bp);
            b1 = *(const float4*)(Bp + 4);
        }

#pragma unroll
        for (int kk = 0; kk < BK; kk++) {
            float4 av0 = *(const float4*)&sA[buf][kk][ty * 8];
            float4 av1 = *(const float4*)&sA[buf][kk][ty * 8 + 4];
            float4 bv0 = *(const float4*)&sB[buf][kk][tx * 8];
            float4 bv1 = *(const float4*)&sB[buf][kk][tx * 8 + 4];
            float am[8] = {av0.x, av0.y, av0.z, av0.w, av1.x, av1.y, av1.z, av1.w};
            float bn[8] = {bv0.x, bv0.y, bv0.z, bv0.w, bv1.x, bv1.y, bv1.z, bv1.w};
#pragma unroll
            for (int i = 0; i < 8; i++)
#pragma unroll
                for (int j = 0; j < 8; j++)
                    acc[i][j] = __fmaf_rn(am[i], bn[j], acc[i][j]);
        }

        if (more) {
            int nb = buf ^ 1;
            sA[nb][lk + 0][lrow] = a0.x; sA[nb][lk + 1][lrow] = a0.y;
            sA[nb][lk + 2][lrow] = a0.z; sA[nb][lk + 3][lrow] = a0.w;
            sA[nb][lk + 4][lrow] = a1.x; sA[nb][lk + 5][lrow] = a1.y;
            sA[nb][lk + 6][lrow] = a1.z; sA[nb][lk + 7][lrow] = a1.w;
            sB[nb][lk + 0][lrow] = b0.x; sB[nb][lk + 1][lrow] = b0.y;
            sB[nb][lk + 2][lrow] = b0.z; sB[nb][lk + 3][lrow] = b0.w;
            sB[nb][lk + 4][lrow] = b1.x; sB[nb][lk + 5][lrow] = b1.y;
            sB[nb][lk + 6][lrow] = b1.z; sB[nb][lk + 7][lrow] = b1.w;
            __syncthreads();
            buf = nb;
        }
    }

    // epilogue: write 8x8 microtile (two float4 per row)
#pragma unroll
    for (int i = 0; i < 8; i++) {
        float* cp = C + (size_t)(m0 + ty * 8 + i) * CO + n0 + tx * 8;
        *(float4*)(cp)     = make_float4(acc[i][0], acc[i][1], acc[i][2], acc[i][3]);
        *(float4*)(cp + 4) = make_float4(acc[i][4], acc[i][5], acc[i][6], acc[i][7]);
    }
}

// ---------------------------------------------------------------------------
// Kernel 3: epilogue — gather 3 rows of G, add F row + bias, ReLU, LayerNorm.
// ---------------------------------------------------------------------------
__global__ __launch_bounds__(CO) void epilogue_kernel(
    const float* __restrict__ G, const float* __restrict__ Fm,
    const int* __restrict__ idx, const float* __restrict__ w,
    const float* __restrict__ bias, const float* __restrict__ gamma,
    const float* __restrict__ beta, float* __restrict__ out) {

    int n = blockIdx.x;
    int o = threadIdx.x;

    int i0 = idx[3 * n], i1 = idx[3 * n + 1], i2 = idx[3 * n + 2];
    float w0 = w[3 * n], w1 = w[3 * n + 1], w2 = w[3 * n + 2];

    float h = w0 * G[(size_t)i0 * CO + o]
            + w1 * G[(size_t)i1 * CO + o]
            + w2 * G[(size_t)i2 * CO + o]
            + Fm[(size_t)n * CO + o] + bias[o];
    h = fmaxf(h, 0.0f);

    float s1 = h, s2 = h * h;
#pragma unroll
    for (int off = 16; off; off >>= 1) {
        s1 += __shfl_xor_sync(0xffffffffu, s1, off);
        s2 += __shfl_xor_sync(0xffffffffu, s2, off);
    }
    __shared__ float p1[8], p2[8], stats[2];
    int warp = o >> 5, lane = o & 31;
    if (lane == 0) { p1[warp] = s1; p2[warp] = s2; }
    __syncthreads();
    if (o == 0) {
        float t1 = 0.f, t2 = 0.f;
#pragma unroll
        for (int i = 0; i < 8; i++) { t1 += p1[i]; t2 += p2[i]; }
        float mu  = t1 * (1.0f / CO);
        float var = t2 * (1.0f / CO) - mu * mu;
        stats[0] = mu;
        stats[1] = rsqrtf(var + 1e-5f);
    }
    __syncthreads();
    float mu = stats[0], rinv = stats[1];
    out[(size_t)n * CO + o] = gamma[o] * (h - mu) * rinv + beta[o];
}

// ---------------------------------------------------------------------------
extern "C" void kernel_launch(void* const* d_in, const int* in_sizes, int n_in,
                              void* d_out, int out_size) {
    const float* cfeat = (const float*)d_in[0];  // [4096, 512]
    const float* cpos  = (const float*)d_in[1];  // [4096, 3]
    const float* ffeat = (const float*)d_in[2];  // [16384, 256]
    const float* fpos  = (const float*)d_in[3];  // [16384, 3]
    const float* W     = (const float*)d_in[4];  // [256, 768]
    const float* bias  = (const float*)d_in[5];  // [256]
    const float* gamma = (const float*)d_in[6];  // [256]
    const float* beta  = (const float*)d_in[7];  // [256]
    float* out = (float*)d_out;

    float *G, *Fm, *wp;
    int* idxp;
    cudaGetSymbolAddress((void**)&G,    g_G);
    cudaGetSymbolAddress((void**)&Fm,   g_F);
    cudaGetSymbolAddress((void**)&idxp, g_idx);
    cudaGetSymbolAddress((void**)&wp,   g_w);

    // kNN (64 KB dynamic shared: all coarse points as float4)
    cudaFuncSetAttribute(knn_kernel, cudaFuncAttributeMaxDynamicSharedMemorySize,
                         NC * (int)sizeof(float4));
    knn_kernel<<<NF / 128, 128, NC * sizeof(float4)>>>(cpos, fpos, idxp, wp);

    // merged dual GEMM: G and F in one launch (fills the whole chip)
    dual_sgemm<<<G_BLOCKS + F_BLOCKS, 256>>>(cfeat, ffeat, W, G, Fm);

    epilogue_kernel<<<NF, CO>>>(G, Fm, idxp, wp, bias, gamma, beta, out);
}